// round 9
// baseline (speedup 1.0000x reference)
#include <cuda_runtime.h>

#define GRID_N 32
#define CELLS  1024
#define SROW   10               // cols per class array (8 + 2 halo)
#define NRWS   34               // 32 rows + top/bottom halo
#define NT     64               // 8x8 blocks of 4x4 cells
#define ESW    4                // half-sweeps per termination check

__global__ void __launch_bounds__(NT, 1)
dijkstra_grid_kernel(const float* __restrict__ wg, float* __restrict__ out)
{
    // dist split by x%4: SA[c][(y+1)*SROW + ((x+4)>>2)], halos = INF
    __shared__ float SA[4][NRWS * SROW];
    __shared__ unsigned short pred[CELLS];
    __shared__ unsigned char  mark[CELLS];
    __shared__ int flags[3];

    volatile float (*S)[NRWS * SROW] = SA;

    const int b  = blockIdx.x;
    const int t  = threadIdx.x;
    const int tx = t & 7;                 // block col 0..7
    const int ty = t >> 3;                // block row 0..7
    const int x0 = tx * 4, y0 = ty * 4;
    const float INF = __int_as_float(0x7f800000);

    // weights: 4 float4 rows (coalesced)
    float ww[4][4];
    {
        const float4* w4 = (const float4*)(wg + (size_t)b * CELLS);
#pragma unroll
        for (int r = 0; r < 4; r++) {
            float4 v = w4[(y0 + r) * 8 + tx];
            ww[r][0] = v.x; ww[r][1] = v.y; ww[r][2] = v.z; ww[r][3] = v.w;
        }
    }

    for (int i = t; i < 4 * NRWS * SROW; i += NT) ((float*)SA)[i] = INF;
    for (int i = t; i < CELLS; i += NT) mark[i] = 0;
    if (t < 3) flags[t] = 0;
    __syncthreads();

    float dd[4][4];
#pragma unroll
    for (int r = 0; r < 4; r++)
#pragma unroll
        for (int j = 0; j < 4; j++) dd[r][j] = INF;
    if (t == 0) dd[0][0] = 0.0f;          // source (0,0)

    // store my tile: cell x0+j has class j, col tx+1; padded row y0+1+r
#define STORE16()                                                         \
    do {                                                                  \
        _Pragma("unroll")                                                 \
        for (int r = 0; r < 4; r++) {                                     \
            S[0][(y0 + 1 + r) * SROW + tx + 1] = dd[r][0];                \
            S[1][(y0 + 1 + r) * SROW + tx + 1] = dd[r][1];                \
            S[2][(y0 + 1 + r) * SROW + tx + 1] = dd[r][2];                \
            S[3][(y0 + 1 + r) * SROW + tx + 1] = dd[r][3];                \
        }                                                                 \
    } while (0)

    STORE16();
    __syncthreads();

    // ---- chaotic min-plus relaxation: 4x4 register Gauss-Seidel per block,
    // Jacobi across blocks via smem. Every candidate is d[nb] + w (RN):
    // exact, monotone-decreasing, reference-attainable path sums; unique
    // fixed point == reference Dijkstra distances bitwise.
    int e = 0;
    for (;; e++) {
        float ss[4][4];
#pragma unroll
        for (int r = 0; r < 4; r++)
#pragma unroll
            for (int j = 0; j < 4; j++) ss[r][j] = dd[r][j];

#pragma unroll
        for (int k = 0; k < ESW; k++) {
            // 20 conflict-free halo loads (old values)
            float t0 = S[3][y0 * SROW + tx];
            float t1 = S[0][y0 * SROW + tx + 1];
            float t2 = S[1][y0 * SROW + tx + 1];
            float t3 = S[2][y0 * SROW + tx + 1];
            float t4 = S[3][y0 * SROW + tx + 1];
            float t5 = S[0][y0 * SROW + tx + 2];
            float b0 = S[3][(y0 + 5) * SROW + tx];
            float b1 = S[0][(y0 + 5) * SROW + tx + 1];
            float b2 = S[1][(y0 + 5) * SROW + tx + 1];
            float b3 = S[2][(y0 + 5) * SROW + tx + 1];
            float b4 = S[3][(y0 + 5) * SROW + tx + 1];
            float b5 = S[0][(y0 + 5) * SROW + tx + 2];
            float l0 = S[3][(y0 + 1) * SROW + tx];
            float l1 = S[3][(y0 + 2) * SROW + tx];
            float l2 = S[3][(y0 + 3) * SROW + tx];
            float l3 = S[3][(y0 + 4) * SROW + tx];
            float r0 = S[0][(y0 + 1) * SROW + tx + 2];
            float r1 = S[0][(y0 + 2) * SROW + tx + 2];
            float r2 = S[0][(y0 + 3) * SROW + tx + 2];
            float r3 = S[0][(y0 + 4) * SROW + tx + 2];

            // static (halo-only) contribution per boundary cell
            float hs[4][4];
            hs[0][0] = fminf(fminf(t0, t1), fminf(t2, fminf(l0, l1)));
            hs[0][1] = fminf(t1, fminf(t2, t3));
            hs[0][2] = fminf(t2, fminf(t3, t4));
            hs[0][3] = fminf(fminf(t3, t4), fminf(t5, fminf(r0, r1)));
            hs[1][0] = fminf(l0, fminf(l1, l2));
            hs[1][1] = INF; hs[1][2] = INF;
            hs[1][3] = fminf(r0, fminf(r1, r2));
            hs[2][0] = fminf(l1, fminf(l2, l3));
            hs[2][1] = INF; hs[2][2] = INF;
            hs[2][3] = fminf(r1, fminf(r2, r3));
            hs[3][0] = fminf(fminf(l2, l3), fminf(b0, fminf(b1, b2)));
            hs[3][1] = fminf(b1, fminf(b2, b3));
            hs[3][2] = fminf(b2, fminf(b3, b4));
            hs[3][3] = fminf(fminf(r2, r3), fminf(b3, fminf(b4, b5)));

#define RELAX(R, J)                                                       \
            {                                                             \
                float m = hs[R][J];                                       \
                _Pragma("unroll")                                         \
                for (int dy = -1; dy <= 1; dy++)                          \
                _Pragma("unroll")                                         \
                for (int dx = -1; dx <= 1; dx++) {                        \
                    if (dy == 0 && dx == 0) continue;                     \
                    int rr = (R) + dy, jj = (J) + dx;                     \
                    if (rr >= 0 && rr < 4 && jj >= 0 && jj < 4)           \
                        m = fminf(m, dd[rr][jj]);                         \
                }                                                         \
                dd[R][J] = fminf(dd[R][J], m + ww[R][J]);                 \
            }

            if ((k & 1) == 0) {       // forward row-major GS
#pragma unroll
                for (int r = 0; r < 4; r++)
#pragma unroll
                    for (int j = 0; j < 4; j++) RELAX(r, j)
            } else {                  // backward
#pragma unroll
                for (int r = 3; r >= 0; r--)
#pragma unroll
                    for (int j = 3; j >= 0; j--) RELAX(r, j)
            }
#undef RELAX
            STORE16();
        }

        // registers monotone-decreasing: unchanged epoch everywhere => done
        int ch = 0;
#pragma unroll
        for (int r = 0; r < 4; r++)
#pragma unroll
            for (int j = 0; j < 4; j++) ch |= (dd[r][j] != ss[r][j]);
        if (ch) flags[e % 3] = 1;
        if (t == 0) flags[(e + 1) % 3] = 0;   // reset ordered by the barriers
        __syncthreads();
        if (!flags[e % 3]) break;             // uniform exit
    }
#undef STORE16

    // ---- predecessor = argmin over 8 neighbor distances (unique a.s.) ----
    {
        const int dy8[8] = {-1, -1, -1, 0, 0, 1, 1, 1};
        const int dx8[8] = {-1,  0,  1,-1, 1,-1, 0, 1};
#pragma unroll
        for (int r = 0; r < 4; r++)
#pragma unroll
            for (int j = 0; j < 4; j++) {
                const int y = y0 + r, x = x0 + j;
                float bd = INF; int bi = 0;
#pragma unroll
                for (int k = 0; k < 8; k++) {
                    int yy = y + dy8[k], xx = x + dx8[k];
                    float v = SA[(xx + 4) & 3][(yy + 1) * SROW + ((xx + 4) >> 2)];
                    if (v < bd) { bd = v; bi = yy * GRID_N + xx; }
                }
                pred[y * GRID_N + x] = (unsigned short)bi;
            }
    }
    __syncthreads();

    // ---- backtrack from (31,31); pred chain strictly decreases dist ----
    if (t == 0) {
        int cur = CELLS - 1;
        for (int i = 0; i < CELLS; i++) {
            mark[cur] = 1;
            if (cur == 0) break;
            cur = pred[cur];
        }
    }
    __syncthreads();

    // ---- coalesced float4 output ----
    {
        float4* o4 = (float4*)(out + (size_t)b * CELLS);
#pragma unroll
        for (int r = 0; r < 4; r++) {
            const int base = (y0 + r) * GRID_N + x0;
            o4[(y0 + r) * 8 + tx] = make_float4(
                mark[base]     ? 1.0f : 0.0f,
                mark[base + 1] ? 1.0f : 0.0f,
                mark[base + 2] ? 1.0f : 0.0f,
                mark[base + 3] ? 1.0f : 0.0f);
        }
    }
}

extern "C" void kernel_launch(void* const* d_in, const int* in_sizes, int n_in,
                              void* d_out, int out_size)
{
    const float* w = (const float*)d_in[0];
    float* out = (float*)d_out;
    int batches = in_sizes[0] / CELLS;     // 128
    dijkstra_grid_kernel<<<batches, NT>>>(w, out);
}

// round 10
// speedup vs baseline: 1.1830x; 1.1830x over previous
#include <cuda_runtime.h>

#define GRID_N 32
#define CELLS  1024
#define SROW   24              // smem row stride: 2*SROW % 32 == 16 -> conflict-free
#define NROWS  34
#define NT     256
#define ESW    4

__global__ void __launch_bounds__(NT, 1)
dijkstra_grid_kernel(const float* __restrict__ wg, float* __restrict__ out)
{
    __shared__ float Ea[NROWS * SROW];      // even-x columns
    __shared__ float Oa[NROWS * SROW];      // odd-x columns
    __shared__ unsigned short pred[CELLS];
    __shared__ unsigned short pred2[CELLS]; // pred^2
    __shared__ unsigned short pred3[CELLS]; // pred^3
    __shared__ unsigned short pred4[CELLS]; // pred^4
    __shared__ unsigned char  mark[CELLS];
    __shared__ int flags[3];

    volatile float* E = Ea;
    volatile float* O = Oa;

    const int b  = blockIdx.x;
    const int t  = threadIdx.x;
    const int tx = t & 15;
    const int ty = t >> 4;
    const float INF = __int_as_float(0x7f800000);

    const int x0 = tx * 2, y0 = ty * 2;
    const int rt = y0, ra = y0 + 1, rc = y0 + 2, rb = y0 + 3;

    const float2* w2 = (const float2*)(wg + (size_t)b * CELLS);
    const float2 wAB = w2[y0 * 16 + tx];
    const float2 wCD = w2[(y0 + 1) * 16 + tx];
    const float wa = wAB.x, wb = wAB.y, wc = wCD.x, wd = wCD.y;

    for (int i = t; i < NROWS * SROW; i += NT) { Ea[i] = INF; Oa[i] = INF; }
    for (int i = t; i < CELLS; i += NT) mark[i] = 0;
    if (t < 3) flags[t] = 0;
    __syncthreads();

    float a = (t == 0) ? 0.0f : INF;        // (y0,   x0)
    float bv = INF;                          // (y0,   x0+1)
    float c = INF;                           // (y0+1, x0)
    float d = INF;                           // (y0+1, x0+1)
    Ea[ra * SROW + tx] = a;  Oa[ra * SROW + tx + 1] = bv;
    Ea[rc * SROW + tx] = c;  Oa[rc * SROW + tx + 1] = d;
    __syncthreads();

    // ---- chaotic min-plus relaxation: GS inside the 2x2 block (registers),
    // Jacobi across blocks (smem). Every candidate is d[nb] + w (RN): exact,
    // monotone-decreasing, reference-attainable path sums. Unique fixed
    // point == reference Dijkstra distances bitwise.  (identical to R7)
    int e = 0;
    for (;; e++) {
        const float sa = a, sb = bv, sc = c, sd = d;
#pragma unroll
        for (int k = 0; k < ESW; k++) {
            float tl  = O[rt * SROW + tx];
            float tce = E[rt * SROW + tx];
            float tco = O[rt * SROW + tx + 1];
            float tre = E[rt * SROW + tx + 1];
            float bl  = O[rb * SROW + tx];
            float bce = E[rb * SROW + tx];
            float bco = O[rb * SROW + tx + 1];
            float bre = E[rb * SROW + tx + 1];
            float l0  = O[ra * SROW + tx];
            float l1  = O[rc * SROW + tx];
            float r0  = E[ra * SROW + tx + 1];
            float r1  = E[rc * SROW + tx + 1];

            // forward Gauss-Seidel: a, b, c, d
            a  = fminf(a,  fminf(fminf(fminf(tl, tce), fminf(tco, l0)),
                                 fminf(fminf(bv, l1),  fminf(c, d))) + wa);
            bv = fminf(bv, fminf(fminf(fminf(tce, tco), fminf(tre, a)),
                                 fminf(fminf(r0, c),    fminf(d, r1))) + wb);
            c  = fminf(c,  fminf(fminf(fminf(l0, a),   fminf(bv, l1)),
                                 fminf(fminf(d, bl),   fminf(bce, bco))) + wc);
            d  = fminf(d,  fminf(fminf(fminf(a, bv),   fminf(r0, c)),
                                 fminf(fminf(r1, bce), fminf(bco, bre))) + wd);
            // backward: c, b, a
            c  = fminf(c,  fminf(fminf(fminf(l0, a),   fminf(bv, l1)),
                                 fminf(fminf(d, bl),   fminf(bce, bco))) + wc);
            bv = fminf(bv, fminf(fminf(fminf(tce, tco), fminf(tre, a)),
                                 fminf(fminf(r0, c),    fminf(d, r1))) + wb);
            a  = fminf(a,  fminf(fminf(fminf(tl, tce), fminf(tco, l0)),
                                 fminf(fminf(bv, l1),  fminf(c, d))) + wa);

            E[ra * SROW + tx] = a;  O[ra * SROW + tx + 1] = bv;
            E[rc * SROW + tx] = c;  O[rc * SROW + tx + 1] = d;
        }
        if ((a != sa) | (bv != sb) | (c != sc) | (d != sd)) flags[e % 3] = 1;
        if (t == 0) flags[(e + 1) % 3] = 0;   // reset ordered by the barriers
        __syncthreads();
        if (!flags[e % 3]) break;             // uniform exit
    }

    // ---- predecessor = argmin over 8 neighbor distances (unique a.s.) ----
    {
        float tl  = Oa[rt * SROW + tx];
        float tce = Ea[rt * SROW + tx];
        float tco = Oa[rt * SROW + tx + 1];
        float tre = Ea[rt * SROW + tx + 1];
        float bl  = Oa[rb * SROW + tx];
        float bce = Ea[rb * SROW + tx];
        float bco = Oa[rb * SROW + tx + 1];
        float bre = Ea[rb * SROW + tx + 1];
        float l0  = Oa[ra * SROW + tx];
        float l1  = Oa[rc * SROW + tx];
        float r0  = Ea[ra * SROW + tx + 1];
        float r1  = Ea[rc * SROW + tx + 1];

        const int A = y0 * GRID_N + x0, B = A + 1, C = A + GRID_N, D = A + GRID_N + 1;

#define ARGMIN8(v1,i1,v2,i2,v3,i3,v4,i4,v5,i5,v6,i6,v7,i7,v8,i8, OUTCELL)      \
        {                                                                       \
            float bd = INF; int bi = 0;                                         \
            if (v1 < bd) { bd = v1; bi = i1; }                                  \
            if (v2 < bd) { bd = v2; bi = i2; }                                  \
            if (v3 < bd) { bd = v3; bi = i3; }                                  \
            if (v4 < bd) { bd = v4; bi = i4; }                                  \
            if (v5 < bd) { bd = v5; bi = i5; }                                  \
            if (v6 < bd) { bd = v6; bi = i6; }                                  \
            if (v7 < bd) { bd = v7; bi = i7; }                                  \
            if (v8 < bd) { bd = v8; bi = i8; }                                  \
            pred[OUTCELL] = (unsigned short)bi;                                 \
        }

        ARGMIN8(tl, A-33, tce, A-32, tco, A-31, l0, A-1, bv, A+1,
                l1, A+31, c, A+32, d, A+33, A)
        ARGMIN8(tce, B-33, tco, B-32, tre, B-31, a, B-1, r0, B+1,
                c, B+31, d, B+32, r1, B+33, B)
        ARGMIN8(l0, C-33, a, C-32, bv, C-31, l1, C-1, d, C+1,
                bl, C+31, bce, C+32, bco, C+33, C)
        ARGMIN8(a, D-33, bv, D-32, r0, D-31, c, D-1, r1, D+1,
                bce, D+31, bco, D+32, bre, D+33, D)
#undef ARGMIN8
    }
    __syncthreads();

    // ---- skip-pointer construction: pred2 = pred∘pred ----
#pragma unroll
    for (int i = 0; i < 4; i++) {
        const int cell = t + i * NT;
        pred2[cell] = pred[pred[cell]];
    }
    __syncthreads();
    // pred3 = pred∘pred2, pred4 = pred2∘pred2
#pragma unroll
    for (int i = 0; i < 4; i++) {
        const int cell = t + i * NT;
        const int q = pred2[cell];
        pred3[cell] = pred[q];
        pred4[cell] = pred2[q];
    }
    __syncthreads();

    // ---- backtrack from (31,31), 4 chain cells per iteration ----
    // pred chain strictly decreases dist, so it reaches cell 0; stop at the
    // first 0 in the window before using the 4-step jump.
    if (t == 0) {
        int cur = CELLS - 1;
        for (int i = 0; i < CELLS / 4 + 2; i++) {
            const int m1 = pred[cur];
            const int m2 = pred2[cur];
            const int m3 = pred3[cur];
            const int nx = pred4[cur];
            mark[cur] = 1;
            if (cur == 0) break;
            mark[m1] = 1;
            if (m1 == 0) break;
            mark[m2] = 1;
            if (m2 == 0) break;
            mark[m3] = 1;
            if (m3 == 0) break;
            cur = nx;
        }
    }
    __syncthreads();

    // ---- coalesced float2 output ----
    {
        float2* o2 = (float2*)(out + (size_t)b * CELLS);
        const int A = y0 * GRID_N + x0;
        o2[y0 * 16 + tx]       = make_float2(mark[A]      ? 1.0f : 0.0f,
                                             mark[A + 1]  ? 1.0f : 0.0f);
        o2[(y0 + 1) * 16 + tx] = make_float2(mark[A + 32] ? 1.0f : 0.0f,
                                             mark[A + 33] ? 1.0f : 0.0f);
    }
}

extern "C" void kernel_launch(void* const* d_in, const int* in_sizes, int n_in,
                              void* d_out, int out_size)
{
    const float* w = (const float*)d_in[0];
    float* out = (float*)d_out;
    int batches = in_sizes[0] / CELLS;     // 128
    dijkstra_grid_kernel<<<batches, NT>>>(w, out);
}